// round 15
// baseline (speedup 1.0000x reference)
#include <cuda_runtime.h>
#include <cstdint>

typedef unsigned long long ull;
typedef unsigned int uint;

#define D_IN   4096
#define R_RANK 16
#define O_OUT  4096
#define M_TOT  8192
#define SCALE  2.0f          // alpha/rank = 32/16
#define MT     16            // tokens per CTA (p1)
#define TOKP2  128           // tokens per CTA (p2)

// ---- device scratch: h as plain float [m][16] ----
__device__ __align__(16) float g_h32[M_TOT * R_RANK];

// ---- tf32 mma helpers (base ISA, sm_80+) ----
__device__ __forceinline__ uint f2tf(float f) {   // round-to-nearest tf32
    uint r; asm("cvt.rna.tf32.f32 %0, %1;" : "=r"(r) : "f"(f)); return r;
}
__device__ __forceinline__ void mma8(float* d, uint a0, uint a1, uint a2, uint a3,
                                     uint b0, uint b1) {
    asm volatile(
        "mma.sync.aligned.m16n8k8.row.col.f32.tf32.tf32.f32 "
        "{%0,%1,%2,%3}, {%4,%5,%6,%7}, {%8,%9}, {%0,%1,%2,%3};"
        : "+f"(d[0]), "+f"(d[1]), "+f"(d[2]), "+f"(d[3])
        : "r"(a0), "r"(a1), "r"(a2), "r"(a3), "r"(b0), "r"(b1));
}

// ===================== kernel 1: h = SCALE * (x @ A^T), direct-LDG mma ========
// 512 CTAs x 128 threads (4 warps = 1 m16-tile x 4 k-quarters). No staging:
// x fragments via LDG.32 (DRAM-stream), A fragments via LDG.32 (L2-hot),
// hi/lo split in regs (validated R12/R14 math). smem only for k-reduction.
__global__ void __launch_bounds__(128, 4)
lora_mma1(const float* __restrict__ x, const float* __restrict__ A) {
    __shared__ float red[3 * 512];   // 6 KB: k-quarter partials

    const int tid  = threadIdx.x;
    const int lane = tid & 31;
    const int kh   = tid >> 5;       // k-quarter (0..3)
    const int m0   = blockIdx.x * MT;
    const int r0   = lane >> 2;
    const int c0   = lane & 3;

    float d[4][4];                   // [0:hi r0-7, 1:hi r8-15, 2:lo r0-7, 3:lo r8-15]
    #pragma unroll
    for (int nt = 0; nt < 4; ++nt)
        #pragma unroll
        for (int j = 0; j < 4; ++j) d[nt][j] = 0.0f;

    const float* xr  = x + (size_t)(m0 + r0) * D_IN;
    const float* xr8 = xr + 8 * D_IN;
    const float* ar  = A + (size_t)r0 * D_IN;
    const float* ar8 = ar + 8 * D_IN;
    const int kbase = kh * 1024 + c0;    // this warp's contiguous 4KB k-range

    #pragma unroll 4
    for (int kk = 0; kk < 128; ++kk) {   // 128 k8-steps per warp
        const int k0 = kbase + kk * 8;
        // A-operand fragment: x rows (tf32 rna, zero-mean)
        uint a0 = f2tf(xr[k0]);
        uint a1 = f2tf(xr8[k0]);
        uint a2 = f2tf(xr[k0 + 4]);
        uint a3 = f2tf(xr8[k0 + 4]);
        // B-operand: LoRA-A rows, hi/lo split (hi exact tf32)
        float v00 = ar[k0];
        float v01 = ar[k0 + 4];
        float v10 = ar8[k0];
        float v11 = ar8[k0 + 4];
        uint h00 = __float_as_uint(v00) & 0xFFFFE000u;
        uint h01 = __float_as_uint(v01) & 0xFFFFE000u;
        uint h10 = __float_as_uint(v10) & 0xFFFFE000u;
        uint h11 = __float_as_uint(v11) & 0xFFFFE000u;
        float l00 = v00 - __uint_as_float(h00);
        float l01 = v01 - __uint_as_float(h01);
        float l10 = v10 - __uint_as_float(h10);
        float l11 = v11 - __uint_as_float(h11);
        mma8(d[0], a0, a1, a2, a3, h00, h01);
        mma8(d[1], a0, a1, a2, a3, h10, h11);
        mma8(d[2], a0, a1, a2, a3, __float_as_uint(l00), __float_as_uint(l01));
        mma8(d[3], a0, a1, a2, a3, __float_as_uint(l10), __float_as_uint(l11));
    }

    // k-quarter reduction via smem
    if (kh != 0) {
        #pragma unroll
        for (int nt = 0; nt < 4; ++nt)
            #pragma unroll
            for (int j = 0; j < 4; ++j)
                red[(kh - 1) * 512 + nt * 128 + j * 32 + lane] = d[nt][j];
    }
    __syncthreads();
    if (kh == 0) {
        #pragma unroll
        for (int q = 0; q < 3; ++q)
            #pragma unroll
            for (int nt = 0; nt < 4; ++nt)
                #pragma unroll
                for (int j = 0; j < 4; ++j)
                    d[nt][j] += red[q * 512 + nt * 128 + j * 32 + lane];

        // fold hi+lo, scale, store (validated D mapping: regs 0,1 -> row r0
        // cols 2c0,2c0+1; regs 2,3 -> row r0+8).
        float e0 = (d[0][0] + d[2][0]) * SCALE, e1 = (d[0][1] + d[2][1]) * SCALE;
        float e2 = (d[0][2] + d[2][2]) * SCALE, e3 = (d[0][3] + d[2][3]) * SCALE;
        float f0 = (d[1][0] + d[3][0]) * SCALE, f1 = (d[1][1] + d[3][1]) * SCALE;
        float f2 = (d[1][2] + d[3][2]) * SCALE, f3 = (d[1][3] + d[3][3]) * SCALE;
        *(float2*)(g_h32 + (size_t)(m0 + r0) * 16 + 2 * c0)         = make_float2(e0, e1);
        *(float2*)(g_h32 + (size_t)(m0 + r0) * 16 + 8 + 2 * c0)     = make_float2(f0, f1);
        *(float2*)(g_h32 + (size_t)(m0 + r0 + 8) * 16 + 2 * c0)     = make_float2(e2, e3);
        *(float2*)(g_h32 + (size_t)(m0 + r0 + 8) * 16 + 8 + 2 * c0) = make_float2(f2, f3);
    }
}

// ===================== kernel 2: out = h @ B^T, mma.sync tf32 ================
// grid (M/128, O/256) = (64, 16) = 1024 CTAs x 128 threads (4 warps).
// Warp: o-strip 64 (8 n8-tiles), 128 tokens (8 m16-tiles). B frags in regs;
// h staged in smem stride-20 (validated). Stores repacked through a per-warp
// smem region (stride 72, conflict-free phases) -> coalesced STG.128.
__global__ void __launch_bounds__(128, 4)
lora_mma2(const float* __restrict__ B, float* __restrict__ out) {
    __shared__ __align__(16) float sh[TOKP2 * 20];   // 10240 B: h tile
    __shared__ __align__(16) float rp[4][16 * 72];   // 18432 B: repack, per warp

    const int tid  = threadIdx.x;
    const int lane = tid & 31;
    const int warp = tid >> 5;
    const int m0   = blockIdx.x * TOKP2;
    const int o0   = blockIdx.y * 256 + warp * 64;
    const int r0   = lane >> 2;
    const int c0   = lane & 3;

    // B fragments: n-tile j, k-step ks -> B[o0 + j*8 + r0][ks*8 + c0 (+4)]
    uint bf[8][2][2];
    #pragma unroll
    for (int j = 0; j < 8; ++j) {
        const float* br = B + (size_t)(o0 + j * 8 + r0) * R_RANK;
        #pragma unroll
        for (int ks = 0; ks < 2; ++ks) {
            bf[j][ks][0] = f2tf(br[ks * 8 + c0]);
            bf[j][ks][1] = f2tf(br[ks * 8 + c0 + 4]);
        }
    }

    // Stage h tile [128][16] -> smem stride 20 (validated layout)
    #pragma unroll
    for (int t = 0; t < 4; ++t) {
        int q = tid + t * 128;            // float4 index, 0..511
        int m = q >> 2, quad = q & 3;
        float4 v = ((const float4*)(g_h32 + (size_t)m0 * 16))[q];
        *(float4*)(sh + m * 20 + quad * 4) = v;
    }
    __syncthreads();

    float* w = rp[warp];
    #pragma unroll
    for (int mt = 0; mt < 8; ++mt) {
        const float* hw = sh + (mt * 16) * 20;
        // A-operand fragments (validated mapping)
        uint a[2][4];
        #pragma unroll
        for (int ks = 0; ks < 2; ++ks) {
            a[ks][0] = f2tf(hw[r0 * 20 + ks * 8 + c0]);
            a[ks][1] = f2tf(hw[(r0 + 8) * 20 + ks * 8 + c0]);
            a[ks][2] = f2tf(hw[r0 * 20 + ks * 8 + c0 + 4]);
            a[ks][3] = f2tf(hw[(r0 + 8) * 20 + ks * 8 + c0 + 4]);
        }

        float dd[8][4];
        #pragma unroll
        for (int j = 0; j < 8; ++j)
            #pragma unroll
            for (int k = 0; k < 4; ++k) dd[j][k] = 0.0f;

        #pragma unroll
        for (int j = 0; j < 8; ++j) {
            mma8(dd[j], a[0][0], a[0][1], a[0][2], a[0][3], bf[j][0][0], bf[j][0][1]);
            mma8(dd[j], a[1][0], a[1][1], a[1][2], a[1][3], bf[j][1][0], bf[j][1][1]);
        }

        // Repack: D regs 0,1 -> local row r0 cols j*8+2c0; regs 2,3 -> row r0+8.
        #pragma unroll
        for (int j = 0; j < 8; ++j) {
            *(float2*)(w + r0 * 72 + j * 8 + 2 * c0)       = make_float2(dd[j][0], dd[j][1]);
            *(float2*)(w + (r0 + 8) * 72 + j * 8 + 2 * c0) = make_float2(dd[j][2], dd[j][3]);
        }
        __syncwarp();

        // Coalesced STG.128: lanes 0-15 cover one row's 64 floats, 16-31 next.
        #pragma unroll
        for (int i = 0; i < 8; ++i) {
            int row_l = i * 2 + (lane >> 4);
            int q     = lane & 15;
            float4 v = *(const float4*)(w + row_l * 72 + q * 4);
            *(float4*)(out + (size_t)(m0 + mt * 16 + row_l) * O_OUT + o0 + q * 4) = v;
        }
        __syncwarp();   // before next mt overwrites the repack region
    }
}

extern "C" void kernel_launch(void* const* d_in, const int* in_sizes, int n_in,
                              void* d_out, int out_size) {
    const float* x = (const float*)d_in[0];
    const float* A = (const float*)d_in[1];   // [16, 4096]
    const float* B = (const float*)d_in[2];   // [4096, 16]
    float* out = (float*)d_out;

    lora_mma1<<<M_TOT / MT, 128>>>(x, A);     // 512 CTAs
    dim3 g2(M_TOT / TOKP2, O_OUT / 256);      // (64, 16) = 1024 CTAs
    lora_mma2<<<g2, 128>>>(B, out);
}

// round 16
// speedup vs baseline: 1.1654x; 1.1654x over previous
#include <cuda_runtime.h>
#include <cstdint>

typedef unsigned long long ull;
typedef unsigned int uint;

#define D_IN   4096
#define R_RANK 16
#define O_OUT  4096
#define M_TOT  8192
#define SCALE  2.0f          // alpha/rank = 32/16
#define KC     64            // K floats per pipeline chunk (p1)
#define NITER  (D_IN / KC)   // 64
#define MT     32            // tokens per CTA (p1)
#define TOKP2  128           // tokens per CTA (p2)

// ---- device scratch: h as plain float [m][16] ----
__device__ __align__(16) float g_h32[M_TOT * R_RANK];

// ---- async-copy helpers ----
__device__ __forceinline__ uint32_t smem_u32(const void* p) {
    uint32_t a;
    asm("{ .reg .u64 t; cvta.to.shared.u64 t, %1; cvt.u32.u64 %0, t; }"
        : "=r"(a) : "l"(p));
    return a;
}
__device__ __forceinline__ void cpa16(uint32_t dst, const void* src) {
    asm volatile("cp.async.cg.shared.global [%0], [%1], 16;"
                 :: "r"(dst), "l"(src) : "memory");
}
__device__ __forceinline__ void cpa_commit() {
    asm volatile("cp.async.commit_group;" ::: "memory");
}
__device__ __forceinline__ void cpa_wait2() {
    asm volatile("cp.async.wait_group 2;" ::: "memory");
}

// ---- tf32 mma helpers (base ISA, sm_80+) ----
__device__ __forceinline__ uint f2tf(float f) {   // round-to-nearest tf32
    uint r; asm("cvt.rna.tf32.f32 %0, %1;" : "=r"(r) : "f"(f)); return r;
}
__device__ __forceinline__ void mma8(float* d, uint a0, uint a1, uint a2, uint a3,
                                     uint b0, uint b1) {
    asm volatile(
        "mma.sync.aligned.m16n8k8.row.col.f32.tf32.tf32.f32 "
        "{%0,%1,%2,%3}, {%4,%5,%6,%7}, {%8,%9}, {%0,%1,%2,%3};"
        : "+f"(d[0]), "+f"(d[1]), "+f"(d[2]), "+f"(d[3])
        : "r"(a0), "r"(a1), "r"(a2), "r"(a3), "r"(b0), "r"(b1));
}

// ===================== kernel 1: h = SCALE * (x @ A^T), mma.sync tf32 =========
// R12-validated structure: 256 CTAs x 256 threads, MT=32, 4-stage single-sync
// cp.async pipeline. Warp w: m16-tile (w&1), k-quarter (w>>1). Lo-term dropped
// (B = raw tf32 of A). Stage (floats): x[32][68] then A[16][68].
#define XS_F     (MT * 68)               // 2176
#define STAGE_F  (XS_F + 16 * 68)        // 3264 floats = 13056 B
#define SM1_B    (4 * STAGE_F * 4)       // 52224 B dynamic

__device__ __forceinline__ void p1_stage(uint32_t sb, const float* x,
                                         const float* A, int m0, int c, int b,
                                         int tid) {
    const uint32_t base = sb + b * (STAGE_F * 4);
    #pragma unroll
    for (int t = 0; t < 2; ++t) {               // x: 32 rows x 16 16B-units
        int u = tid + t * 256;
        int row = u >> 4, q = u & 15;
        cpa16(base + (row * 68) * 4 + q * 16,
              x + (size_t)(m0 + row) * D_IN + c * KC + q * 4);
    }
    {                                            // A: 16 rows x 16 units
        int row = tid >> 4, q = tid & 15;
        cpa16(base + (XS_F + row * 68) * 4 + q * 16,
              A + (size_t)row * D_IN + c * KC + q * 4);
    }
}

__global__ void __launch_bounds__(256, 2)
lora_mma1(const float* __restrict__ x, const float* __restrict__ A) {
    extern __shared__ __align__(16) float sm[];
    const uint32_t sb = smem_u32(sm);

    const int tid  = threadIdx.x;
    const int lane = tid & 31;
    const int warp = tid >> 5;
    const int wm   = warp & 1;       // m16 tile within 32-token CTA tile
    const int kh   = warp >> 1;      // k-quarter (0..3)
    const int m0   = blockIdx.x * MT;
    const int r0   = lane >> 2;
    const int c0   = lane & 3;

    float d[2][4];                   // [0: A-rows 0-7, 1: A-rows 8-15]
    #pragma unroll
    for (int nt = 0; nt < 2; ++nt)
        #pragma unroll
        for (int j = 0; j < 4; ++j) d[nt][j] = 0.0f;

    // prologue: stage chunks 0..2
    p1_stage(sb, x, A, m0, 0, 0, tid); cpa_commit();
    p1_stage(sb, x, A, m0, 1, 1, tid); cpa_commit();
    p1_stage(sb, x, A, m0, 2, 2, tid); cpa_commit();

    for (int i = 0; i < NITER; ++i) {
        const int b = i & 3;
        cpa_wait2();          // chunk i landed
        __syncthreads();      // visible to all; all warps past compute(i-1)

        // prefetch chunk i+3 into buffer (i+3)&3 == (i-1)&3 (freed by the sync)
        if (i + 3 < NITER) p1_stage(sb, x, A, m0, i + 3, (i + 3) & 3, tid);
        cpa_commit();

        const float* xw = sm + b * STAGE_F + (wm * 16) * 68;
        const float* rw = sm + b * STAGE_F + XS_F;

        #pragma unroll
        for (int ks = 0; ks < 2; ++ks) {
            const int k0 = kh * 16 + ks * 8 + c0;
            // A-operand fragment: x rows (tf32 rna, zero-mean)
            uint a0 = f2tf(xw[r0 * 68 + k0]);
            uint a1 = f2tf(xw[(r0 + 8) * 68 + k0]);
            uint a2 = f2tf(xw[r0 * 68 + k0 + 4]);
            uint a3 = f2tf(xw[(r0 + 8) * 68 + k0 + 4]);
            // B-operand: LoRA-A rows, raw tf32
            uint b00 = f2tf(rw[r0 * 68 + k0]);
            uint b01 = f2tf(rw[r0 * 68 + k0 + 4]);
            uint b10 = f2tf(rw[(r0 + 8) * 68 + k0]);
            uint b11 = f2tf(rw[(r0 + 8) * 68 + k0 + 4]);
            mma8(d[0], a0, a1, a2, a3, b00, b01);
            mma8(d[1], a0, a1, a2, a3, b10, b11);
        }
    }

    // k-quarter reduction via smem (pipeline buffers dead)
    float* red = sm;
    if (kh != 0) {
        #pragma unroll
        for (int nt = 0; nt < 2; ++nt)
            #pragma unroll
            for (int j = 0; j < 4; ++j)
                red[((kh - 1) * 2 + wm) * 512 + nt * 128 + j * 32 + lane] = d[nt][j];
    }
    __syncthreads();
    if (kh == 0) {
        #pragma unroll
        for (int q = 0; q < 3; ++q)
            #pragma unroll
            for (int nt = 0; nt < 2; ++nt)
                #pragma unroll
                for (int j = 0; j < 4; ++j)
                    d[nt][j] += red[(q * 2 + wm) * 512 + nt * 128 + j * 32 + lane];

        // scale + store plain-float h[m][16] (validated D mapping: regs 0,1 ->
        // token-row r0, h-cols 2c0,2c0+1 (nt0) / 8+2c0 (nt1); regs 2,3 -> r0+8)
        const int mlo = m0 + wm * 16 + r0;
        float e0 = d[0][0] * SCALE, e1 = d[0][1] * SCALE;
        float e2 = d[0][2] * SCALE, e3 = d[0][3] * SCALE;
        float f0 = d[1][0] * SCALE, f1 = d[1][1] * SCALE;
        float f2 = d[1][2] * SCALE, f3 = d[1][3] * SCALE;
        *(float2*)(g_h32 + (size_t)mlo * 16 + 2 * c0)           = make_float2(e0, e1);
        *(float2*)(g_h32 + (size_t)mlo * 16 + 8 + 2 * c0)       = make_float2(f0, f1);
        *(float2*)(g_h32 + (size_t)(mlo + 8) * 16 + 2 * c0)     = make_float2(e2, e3);
        *(float2*)(g_h32 + (size_t)(mlo + 8) * 16 + 8 + 2 * c0) = make_float2(f2, f3);
    }
}

// ===================== kernel 2: out = h @ B^T, mma.sync tf32 (R15, verbatim) =
__global__ void __launch_bounds__(128, 4)
lora_mma2(const float* __restrict__ B, float* __restrict__ out) {
    __shared__ __align__(16) float sh[TOKP2 * 20];   // 10240 B: h tile
    __shared__ __align__(16) float rp[4][16 * 72];   // 18432 B: repack, per warp

    const int tid  = threadIdx.x;
    const int lane = tid & 31;
    const int warp = tid >> 5;
    const int m0   = blockIdx.x * TOKP2;
    const int o0   = blockIdx.y * 256 + warp * 64;
    const int r0   = lane >> 2;
    const int c0   = lane & 3;

    // B fragments: n-tile j, k-step ks -> B[o0 + j*8 + r0][ks*8 + c0 (+4)]
    uint bf[8][2][2];
    #pragma unroll
    for (int j = 0; j < 8; ++j) {
        const float* br = B + (size_t)(o0 + j * 8 + r0) * R_RANK;
        #pragma unroll
        for (int ks = 0; ks < 2; ++ks) {
            bf[j][ks][0] = f2tf(br[ks * 8 + c0]);
            bf[j][ks][1] = f2tf(br[ks * 8 + c0 + 4]);
        }
    }

    // Stage h tile [128][16] -> smem stride 20
    #pragma unroll
    for (int t = 0; t < 4; ++t) {
        int q = tid + t * 128;            // float4 index, 0..511
        int m = q >> 2, quad = q & 3;
        float4 v = ((const float4*)(g_h32 + (size_t)m0 * 16))[q];
        *(float4*)(sh + m * 20 + quad * 4) = v;
    }
    __syncthreads();

    float* w = rp[warp];
    #pragma unroll
    for (int mt = 0; mt < 8; ++mt) {
        const float* hw = sh + (mt * 16) * 20;
        uint a[2][4];
        #pragma unroll
        for (int ks = 0; ks < 2; ++ks) {
            a[ks][0] = f2tf(hw[r0 * 20 + ks * 8 + c0]);
            a[ks][1] = f2tf(hw[(r0 + 8) * 20 + ks * 8 + c0]);
            a[ks][2] = f2tf(hw[r0 * 20 + ks * 8 + c0 + 4]);
            a[ks][3] = f2tf(hw[(r0 + 8) * 20 + ks * 8 + c0 + 4]);
        }

        float dd[8][4];
        #pragma unroll
        for (int j = 0; j < 8; ++j)
            #pragma unroll
            for (int k = 0; k < 4; ++k) dd[j][k] = 0.0f;

        #pragma unroll
        for (int j = 0; j < 8; ++j) {
            mma8(dd[j], a[0][0], a[0][1], a[0][2], a[0][3], bf[j][0][0], bf[j][0][1]);
            mma8(dd[j], a[1][0], a[1][1], a[1][2], a[1][3], bf[j][1][0], bf[j][1][1]);
        }

        // Repack -> per-warp smem, then coalesced STG.128
        #pragma unroll
        for (int j = 0; j < 8; ++j) {
            *(float2*)(w + r0 * 72 + j * 8 + 2 * c0)       = make_float2(dd[j][0], dd[j][1]);
            *(float2*)(w + (r0 + 8) * 72 + j * 8 + 2 * c0) = make_float2(dd[j][2], dd[j][3]);
        }
        __syncwarp();

        #pragma unroll
        for (int i = 0; i < 8; ++i) {
            int row_l = i * 2 + (lane >> 4);
            int q     = lane & 15;
            float4 v = *(const float4*)(w + row_l * 72 + q * 4);
            *(float4*)(out + (size_t)(m0 + mt * 16 + row_l) * O_OUT + o0 + q * 4) = v;
        }
        __syncwarp();   // before next mt overwrites the repack region
    }
}

extern "C" void kernel_launch(void* const* d_in, const int* in_sizes, int n_in,
                              void* d_out, int out_size) {
    const float* x = (const float*)d_in[0];
    const float* A = (const float*)d_in[1];   // [16, 4096]
    const float* B = (const float*)d_in[2];   // [4096, 16]
    float* out = (float*)d_out;

    cudaFuncSetAttribute(lora_mma1, cudaFuncAttributeMaxDynamicSharedMemorySize,
                         SM1_B);

    lora_mma1<<<M_TOT / MT, 256, SM1_B>>>(x, A);   // 256 CTAs
    dim3 g2(M_TOT / TOKP2, O_OUT / 256);           // (64, 16) = 1024 CTAs
    lora_mma2<<<g2, 128>>>(B, out);
}

// round 17
// speedup vs baseline: 1.4580x; 1.2511x over previous
#include <cuda_runtime.h>
#include <cstdint>

typedef unsigned long long ull;
typedef unsigned int uint;

#define D_IN   4096
#define R_RANK 16
#define O_OUT  4096
#define M_TOT  8192
#define SCALE  2.0f          // alpha/rank = 32/16
#define KC     128           // K floats per pipeline chunk (p1)
#define NITER  (D_IN / KC)   // 32
#define MT     32            // tokens per CTA (p1)
#define TOKP2  128           // tokens per CTA (p2)

// ---- device scratch: h as plain float [m][16] ----
__device__ __align__(16) float g_h32[M_TOT * R_RANK];

// ---- async-copy helpers ----
__device__ __forceinline__ uint32_t smem_u32(const void* p) {
    uint32_t a;
    asm("{ .reg .u64 t; cvta.to.shared.u64 t, %1; cvt.u32.u64 %0, t; }"
        : "=r"(a) : "l"(p));
    return a;
}
__device__ __forceinline__ void cpa16(uint32_t dst, const void* src) {
    asm volatile("cp.async.cg.shared.global [%0], [%1], 16;"
                 :: "r"(dst), "l"(src) : "memory");
}
__device__ __forceinline__ void cpa_commit() {
    asm volatile("cp.async.commit_group;" ::: "memory");
}
__device__ __forceinline__ void cpa_wait2() {
    asm volatile("cp.async.wait_group 2;" ::: "memory");
}

// ---- tf32 mma helpers (base ISA, sm_80+) ----
__device__ __forceinline__ uint f2tf(float f) {   // round-to-nearest tf32
    uint r; asm("cvt.rna.tf32.f32 %0, %1;" : "=r"(r) : "f"(f)); return r;
}
__device__ __forceinline__ void mma8(float* d, uint a0, uint a1, uint a2, uint a3,
                                     uint b0, uint b1) {
    asm volatile(
        "mma.sync.aligned.m16n8k8.row.col.f32.tf32.tf32.f32 "
        "{%0,%1,%2,%3}, {%4,%5,%6,%7}, {%8,%9}, {%0,%1,%2,%3};"
        : "+f"(d[0]), "+f"(d[1]), "+f"(d[2]), "+f"(d[3])
        : "r"(a0), "r"(a1), "r"(a2), "r"(a3), "r"(b0), "r"(b1));
}

// ===================== kernel 1: h = SCALE * (x @ A^T), mma.sync tf32 =========
// 256 CTAs x 256 threads, MT=32, KC=128 (32 sync points), 4-stage single-sync
// cp.async pipeline, 3 chunks (75 KB/CTA) in flight. Warp w: m16-tile (w&1),
// k-quarter (w>>1). B-operand = raw tf32 of LoRA-A (lo-term dropped, R16).
// Stage (floats, row stride 132): x[32][132] then A[16][132].
#define RS       132                     // row stride (128 + 4 pad)
#define XS_F     (MT * RS)               // 4224
#define STAGE_F  (XS_F + 16 * RS)        // 6336 floats = 25344 B
#define SM1_B    (4 * STAGE_F * 4)       // 101376 B dynamic

__device__ __forceinline__ void p1_stage(uint32_t sb, const float* x,
                                         const float* A, int m0, int c, int b,
                                         int tid) {
    const uint32_t base = sb + b * (STAGE_F * 4);
    #pragma unroll
    for (int t = 0; t < 4; ++t) {               // x: 32 rows x 32 16B-units
        int u = tid + t * 256;
        int row = u >> 5, q = u & 31;
        cpa16(base + (row * RS) * 4 + q * 16,
              x + (size_t)(m0 + row) * D_IN + c * KC + q * 4);
    }
    #pragma unroll
    for (int t = 0; t < 2; ++t) {               // A: 16 rows x 32 units
        int u = tid + t * 256;
        int row = u >> 5, q = u & 31;
        cpa16(base + (XS_F + row * RS) * 4 + q * 16,
              A + (size_t)row * D_IN + c * KC + q * 4);
    }
}

__global__ void __launch_bounds__(256, 2)
lora_mma1(const float* __restrict__ x, const float* __restrict__ A) {
    extern __shared__ __align__(16) float sm[];
    const uint32_t sb = smem_u32(sm);

    const int tid  = threadIdx.x;
    const int lane = tid & 31;
    const int warp = tid >> 5;
    const int wm   = warp & 1;       // m16 tile within 32-token CTA tile
    const int kh   = warp >> 1;      // k-quarter (0..3)
    const int m0   = blockIdx.x * MT;
    const int r0   = lane >> 2;
    const int c0   = lane & 3;

    float d[2][4];                   // [0: A-rows 0-7, 1: A-rows 8-15]
    #pragma unroll
    for (int nt = 0; nt < 2; ++nt)
        #pragma unroll
        for (int j = 0; j < 4; ++j) d[nt][j] = 0.0f;

    // prologue: stage chunks 0..2
    p1_stage(sb, x, A, m0, 0, 0, tid); cpa_commit();
    p1_stage(sb, x, A, m0, 1, 1, tid); cpa_commit();
    p1_stage(sb, x, A, m0, 2, 2, tid); cpa_commit();

    for (int i = 0; i < NITER; ++i) {
        const int b = i & 3;
        cpa_wait2();          // chunk i landed
        __syncthreads();      // visible to all; all warps past compute(i-1)

        // prefetch chunk i+3 into buffer (i+3)&3 == (i-1)&3 (freed by the sync)
        if (i + 3 < NITER) p1_stage(sb, x, A, m0, i + 3, (i + 3) & 3, tid);
        cpa_commit();

        const float* xw = sm + b * STAGE_F + (wm * 16) * RS;
        const float* rw = sm + b * STAGE_F + XS_F;

        #pragma unroll
        for (int ks = 0; ks < 4; ++ks) {
            const int k0 = kh * 32 + ks * 8 + c0;
            // A-operand fragment: x rows (tf32 rna, zero-mean)
            uint a0 = f2tf(xw[r0 * RS + k0]);
            uint a1 = f2tf(xw[(r0 + 8) * RS + k0]);
            uint a2 = f2tf(xw[r0 * RS + k0 + 4]);
            uint a3 = f2tf(xw[(r0 + 8) * RS + k0 + 4]);
            // B-operand: LoRA-A rows, raw tf32
            uint b00 = f2tf(rw[r0 * RS + k0]);
            uint b01 = f2tf(rw[r0 * RS + k0 + 4]);
            uint b10 = f2tf(rw[(r0 + 8) * RS + k0]);
            uint b11 = f2tf(rw[(r0 + 8) * RS + k0 + 4]);
            mma8(d[0], a0, a1, a2, a3, b00, b01);
            mma8(d[1], a0, a1, a2, a3, b10, b11);
        }
    }

    // k-quarter reduction via smem (pipeline buffers dead; region = buffer 0)
    float* red = sm;
    if (kh != 0) {
        #pragma unroll
        for (int nt = 0; nt < 2; ++nt)
            #pragma unroll
            for (int j = 0; j < 4; ++j)
                red[((kh - 1) * 2 + wm) * 512 + nt * 128 + j * 32 + lane] = d[nt][j];
    }
    __syncthreads();
    if (kh == 0) {
        #pragma unroll
        for (int q = 0; q < 3; ++q)
            #pragma unroll
            for (int nt = 0; nt < 2; ++nt)
                #pragma unroll
                for (int j = 0; j < 4; ++j)
                    d[nt][j] += red[(q * 2 + wm) * 512 + nt * 128 + j * 32 + lane];

        // scale + store plain-float h[m][16] (validated D mapping)
        const int mlo = m0 + wm * 16 + r0;
        float e0 = d[0][0] * SCALE, e1 = d[0][1] * SCALE;
        float e2 = d[0][2] * SCALE, e3 = d[0][3] * SCALE;
        float f0 = d[1][0] * SCALE, f1 = d[1][1] * SCALE;
        float f2 = d[1][2] * SCALE, f3 = d[1][3] * SCALE;
        *(float2*)(g_h32 + (size_t)mlo * 16 + 2 * c0)           = make_float2(e0, e1);
        *(float2*)(g_h32 + (size_t)mlo * 16 + 8 + 2 * c0)       = make_float2(f0, f1);
        *(float2*)(g_h32 + (size_t)(mlo + 8) * 16 + 2 * c0)     = make_float2(e2, e3);
        *(float2*)(g_h32 + (size_t)(mlo + 8) * 16 + 8 + 2 * c0) = make_float2(f2, f3);
    }
}

// ===================== kernel 2: out = h @ B^T, mma.sync tf32 (R15 + occ 6) ==
__global__ void __launch_bounds__(128, 6)
lora_mma2(const float* __restrict__ B, float* __restrict__ out) {
    __shared__ __align__(16) float sh[TOKP2 * 20];   // 10240 B: h tile
    __shared__ __align__(16) float rp[4][16 * 72];   // 18432 B: repack, per warp

    const int tid  = threadIdx.x;
    const int lane = tid & 31;
    const int warp = tid >> 5;
    const int m0   = blockIdx.x * TOKP2;
    const int o0   = blockIdx.y * 256 + warp * 64;
    const int r0   = lane >> 2;
    const int c0   = lane & 3;

    // B fragments: n-tile j, k-step ks -> B[o0 + j*8 + r0][ks*8 + c0 (+4)]
    uint bf[8][2][2];
    #pragma unroll
    for (int j = 0; j < 8; ++j) {
        const float* br = B + (size_t)(o0 + j * 8 + r0) * R_RANK;
        #pragma unroll
        for (int ks = 0; ks < 2; ++ks) {
            bf[j][ks][0] = f2tf(br[ks * 8 + c0]);
            bf[j][ks][1] = f2tf(br[ks * 8 + c0 + 4]);
        }
    }

    // Stage h tile [128][16] -> smem stride 20
    #pragma unroll
    for (int t = 0; t < 4; ++t) {
        int q = tid + t * 128;            // float4 index, 0..511
        int m = q >> 2, quad = q & 3;
        float4 v = ((const float4*)(g_h32 + (size_t)m0 * 16))[q];
        *(float4*)(sh + m * 20 + quad * 4) = v;
    }
    __syncthreads();

    float* w = rp[warp];
    #pragma unroll
    for (int mt = 0; mt < 8; ++mt) {
        const float* hw = sh + (mt * 16) * 20;
        uint a[2][4];
        #pragma unroll
        for (int ks = 0; ks < 2; ++ks) {
            a[ks][0] = f2tf(hw[r0 * 20 + ks * 8 + c0]);
            a[ks][1] = f2tf(hw[(r0 + 8) * 20 + ks * 8 + c0]);
            a[ks][2] = f2tf(hw[r0 * 20 + ks * 8 + c0 + 4]);
            a[ks][3] = f2tf(hw[(r0 + 8) * 20 + ks * 8 + c0 + 4]);
        }

        float dd[8][4];
        #pragma unroll
        for (int j = 0; j < 8; ++j)
            #pragma unroll
            for (int k = 0; k < 4; ++k) dd[j][k] = 0.0f;

        #pragma unroll
        for (int j = 0; j < 8; ++j) {
            mma8(dd[j], a[0][0], a[0][1], a[0][2], a[0][3], bf[j][0][0], bf[j][0][1]);
            mma8(dd[j], a[1][0], a[1][1], a[1][2], a[1][3], bf[j][1][0], bf[j][1][1]);
        }

        // Repack -> per-warp smem, then coalesced STG.128
        #pragma unroll
        for (int j = 0; j < 8; ++j) {
            *(float2*)(w + r0 * 72 + j * 8 + 2 * c0)       = make_float2(dd[j][0], dd[j][1]);
            *(float2*)(w + (r0 + 8) * 72 + j * 8 + 2 * c0) = make_float2(dd[j][2], dd[j][3]);
        }
        __syncwarp();

        #pragma unroll
        for (int i = 0; i < 8; ++i) {
            int row_l = i * 2 + (lane >> 4);
            int q     = lane & 15;
            float4 v = *(const float4*)(w + row_l * 72 + q * 4);
            *(float4*)(out + (size_t)(m0 + mt * 16 + row_l) * O_OUT + o0 + q * 4) = v;
        }
        __syncwarp();   // before next mt overwrites the repack region
    }
}

extern "C" void kernel_launch(void* const* d_in, const int* in_sizes, int n_in,
                              void* d_out, int out_size) {
    const float* x = (const float*)d_in[0];
    const float* A = (const float*)d_in[1];   // [16, 4096]
    const float* B = (const float*)d_in[2];   // [4096, 16]
    float* out = (float*)d_out;

    cudaFuncSetAttribute(lora_mma1, cudaFuncAttributeMaxDynamicSharedMemorySize,
                         SM1_B);

    lora_mma1<<<M_TOT / MT, 256, SM1_B>>>(x, A);   // 256 CTAs
    dim3 g2(M_TOT / TOKP2, O_OUT / 256);           // (64, 16) = 1024 CTAs
    lora_mma2<<<g2, 128>>>(B, out);
}